// round 1
// baseline (speedup 1.0000x reference)
#include <cuda_runtime.h>

// LinearTimeMMD: source/target [65536, 512] fp32 -> scalar.
// m2 = 32768 pairs; per pair p: rows (2p, 2p+1) of each tensor.
// Pure HBM-streaming reduction. One CTA per pair, 128 threads, float4 loads.

#define M2      32768
#define THREADS 128          // 128 * float4 = 512 floats per row
#define F4_PER_ROW 128       // 512 / 4

__device__ float g_partial[M2];

__global__ __launch_bounds__(THREADS)
void mmd_pair_kernel(const float4* __restrict__ src, const float4* __restrict__ tgt)
{
    const int p = blockIdx.x;
    const int t = threadIdx.x;

    const size_t ro = (size_t)(2 * p)     * F4_PER_ROW;  // odd  (index 2p)
    const size_t re = (size_t)(2 * p + 1) * F4_PER_ROW;  // even (index 2p+1)

    const float4 xo = __ldg(src + ro + t);
    const float4 xe = __ldg(src + re + t);
    const float4 yo = __ldg(tgt + ro + t);
    const float4 ye = __ldg(tgt + re + t);

    float dxx = 0.f, dyy = 0.f, dxy = 0.f, dyx = 0.f;
    {
        float d;
        d = xo.x - xe.x; dxx = fmaf(d, d, dxx);
        d = xo.y - xe.y; dxx = fmaf(d, d, dxx);
        d = xo.z - xe.z; dxx = fmaf(d, d, dxx);
        d = xo.w - xe.w; dxx = fmaf(d, d, dxx);

        d = yo.x - ye.x; dyy = fmaf(d, d, dyy);
        d = yo.y - ye.y; dyy = fmaf(d, d, dyy);
        d = yo.z - ye.z; dyy = fmaf(d, d, dyy);
        d = yo.w - ye.w; dyy = fmaf(d, d, dyy);

        d = xo.x - ye.x; dxy = fmaf(d, d, dxy);
        d = xo.y - ye.y; dxy = fmaf(d, d, dxy);
        d = xo.z - ye.z; dxy = fmaf(d, d, dxy);
        d = xo.w - ye.w; dxy = fmaf(d, d, dxy);

        d = xe.x - yo.x; dyx = fmaf(d, d, dyx);
        d = xe.y - yo.y; dyx = fmaf(d, d, dyx);
        d = xe.z - yo.z; dyx = fmaf(d, d, dyx);
        d = xe.w - yo.w; dyx = fmaf(d, d, dyx);
    }

    // warp tree reduce (4 values)
    #pragma unroll
    for (int off = 16; off > 0; off >>= 1) {
        dxx += __shfl_xor_sync(0xffffffffu, dxx, off);
        dyy += __shfl_xor_sync(0xffffffffu, dyy, off);
        dxy += __shfl_xor_sync(0xffffffffu, dxy, off);
        dyx += __shfl_xor_sync(0xffffffffu, dyx, off);
    }

    __shared__ float4 warp_sums[THREADS / 32];
    const int wid = t >> 5;
    const int lid = t & 31;
    if (lid == 0) warp_sums[wid] = make_float4(dxx, dyy, dxy, dyx);
    __syncthreads();

    if (t == 0) {
        dxx = 0.f; dyy = 0.f; dxy = 0.f; dyx = 0.f;
        #pragma unroll
        for (int w = 0; w < THREADS / 32; ++w) {
            dxx += warp_sums[w].x;
            dyy += warp_sums[w].y;
            dxy += warp_sums[w].z;
            dyx += warp_sums[w].w;
        }

        // bw = sum/4 / KERNEL_MUL^(KERNEL_NUM/2) = sum/4 / 4
        float bw = (dxx + dyy + dxy + dyx) * (1.0f / 16.0f);
        float h = 0.f;
        float mult = 1.f;
        #pragma unroll
        for (int k = 0; k < 5; ++k) {
            float inv = 1.0f / (bw * mult + 1e-6f);
            h += expf(-dxx * inv) + expf(-dyy * inv)
               - expf(-dxy * inv) - expf(-dyx * inv);
            mult *= 2.f;
        }
        g_partial[p] = h;
    }
}

// Single-block deterministic final reduction in double.
__global__ __launch_bounds__(1024)
void mmd_final_kernel(float* __restrict__ out)
{
    const int t = threadIdx.x;
    double acc = 0.0;
    for (int i = t; i < M2; i += 1024)
        acc += (double)g_partial[i];

    #pragma unroll
    for (int off = 16; off > 0; off >>= 1)
        acc += __shfl_xor_sync(0xffffffffu, acc, off);

    __shared__ double warp_sums[32];
    const int wid = t >> 5;
    const int lid = t & 31;
    if (lid == 0) warp_sums[wid] = acc;
    __syncthreads();

    if (wid == 0) {
        double s = (lid < 32) ? warp_sums[lid] : 0.0;
        #pragma unroll
        for (int off = 16; off > 0; off >>= 1)
            s += __shfl_xor_sync(0xffffffffu, s, off);
        if (lid == 0)
            out[0] = (float)(s / (double)M2);
    }
}

extern "C" void kernel_launch(void* const* d_in, const int* in_sizes, int n_in,
                              void* d_out, int out_size)
{
    const float4* src = (const float4*)d_in[0];
    const float4* tgt = (const float4*)d_in[1];
    float* out = (float*)d_out;

    mmd_pair_kernel<<<M2, THREADS>>>(src, tgt);
    mmd_final_kernel<<<1, 1024>>>(out);
}

// round 2
// speedup vs baseline: 1.2851x; 1.2851x over previous
#include <cuda_runtime.h>

// LinearTimeMMD fused single kernel: source/target [65536, 512] fp32 -> scalar.
// m2 = 32768 pairs. Each 256-thread block handles 2 pairs (128 threads each).
// Per-pair h reduced via deterministic fixed-point int64 atomicAdd; the last
// block to finish writes the mean and resets state for graph replay.

#define M2          32768
#define PAIRS_PER_BLK 2
#define THREADS     (128 * PAIRS_PER_BLK)
#define GRID        (M2 / PAIRS_PER_BLK)
#define F4_PER_ROW  128          // 512 floats / 4

// 2^40 fixed-point scale: |h| <= 10 -> |v| < 2^44; sum over 32768 < 2^59.
#define FP_SCALE    1099511627776.0

__device__ long long          g_acc   = 0;
__device__ unsigned int       g_count = 0;

__global__ __launch_bounds__(THREADS)
void mmd_fused_kernel(const float4* __restrict__ src,
                      const float4* __restrict__ tgt,
                      float* __restrict__ out)
{
    const int t   = threadIdx.x;
    const int sub = t >> 7;            // which pair within block (0..1)
    const int lt  = t & 127;           // lane within pair-group
    const int p   = blockIdx.x * PAIRS_PER_BLK + sub;

    const size_t ro = (size_t)(2 * p)     * F4_PER_ROW;  // row 2p   ("odd")
    const size_t re = (size_t)(2 * p + 1) * F4_PER_ROW;  // row 2p+1 ("even")

    const float4 xo = __ldg(src + ro + lt);
    const float4 xe = __ldg(src + re + lt);
    const float4 yo = __ldg(tgt + ro + lt);
    const float4 ye = __ldg(tgt + re + lt);

    float dxx = 0.f, dyy = 0.f, dxy = 0.f, dyx = 0.f;
    {
        float d;
        d = xo.x - xe.x; dxx = fmaf(d, d, dxx);
        d = xo.y - xe.y; dxx = fmaf(d, d, dxx);
        d = xo.z - xe.z; dxx = fmaf(d, d, dxx);
        d = xo.w - xe.w; dxx = fmaf(d, d, dxx);

        d = yo.x - ye.x; dyy = fmaf(d, d, dyy);
        d = yo.y - ye.y; dyy = fmaf(d, d, dyy);
        d = yo.z - ye.z; dyy = fmaf(d, d, dyy);
        d = yo.w - ye.w; dyy = fmaf(d, d, dyy);

        d = xo.x - ye.x; dxy = fmaf(d, d, dxy);
        d = xo.y - ye.y; dxy = fmaf(d, d, dxy);
        d = xo.z - ye.z; dxy = fmaf(d, d, dxy);
        d = xo.w - ye.w; dxy = fmaf(d, d, dxy);

        d = xe.x - yo.x; dyx = fmaf(d, d, dyx);
        d = xe.y - yo.y; dyx = fmaf(d, d, dyx);
        d = xe.z - yo.z; dyx = fmaf(d, d, dyx);
        d = xe.w - yo.w; dyx = fmaf(d, d, dyx);
    }

    // warp tree reduce (4 values)
    #pragma unroll
    for (int off = 16; off > 0; off >>= 1) {
        dxx += __shfl_xor_sync(0xffffffffu, dxx, off);
        dyy += __shfl_xor_sync(0xffffffffu, dyy, off);
        dxy += __shfl_xor_sync(0xffffffffu, dxy, off);
        dyx += __shfl_xor_sync(0xffffffffu, dyx, off);
    }

    // cross-warp reduce within each 128-thread pair-group (4 warps each)
    __shared__ float4 warp_sums[THREADS / 32];   // 8 entries
    const int wid = t >> 5;                      // global warp id 0..7
    const int lid = t & 31;
    if (lid == 0) warp_sums[wid] = make_float4(dxx, dyy, dxy, dyx);
    __syncthreads();

    if (lt == 0) {
        const int wbase = sub * 4;
        dxx = 0.f; dyy = 0.f; dxy = 0.f; dyx = 0.f;
        #pragma unroll
        for (int w = 0; w < 4; ++w) {
            float4 s = warp_sums[wbase + w];
            dxx += s.x; dyy += s.y; dxy += s.z; dyx += s.w;
        }

        // bw = sum/4 / KERNEL_MUL^(KERNEL_NUM/2) = sum/16
        float bw = (dxx + dyy + dxy + dyx) * (1.0f / 16.0f);
        float h = 0.f;
        float mult = 1.f;
        #pragma unroll
        for (int k = 0; k < 5; ++k) {
            float inv = 1.0f / (bw * mult + 1e-6f);
            h += expf(-dxx * inv) + expf(-dyy * inv)
               - expf(-dxy * inv) - expf(-dyx * inv);
            mult *= 2.f;
        }

        long long v = (long long)llrint((double)h * FP_SCALE);
        atomicAdd((unsigned long long*)&g_acc, (unsigned long long)v);
    }
    __syncthreads();   // ensure both pair-groups' atomics issued before count

    if (t == 0) {
        __threadfence();
        unsigned int done = atomicAdd(&g_count, 1u);
        if (done == GRID - 1) {
            // all other blocks' acc-adds are visible (they fenced before count)
            long long acc = g_acc;
            out[0] = (float)(((double)acc / FP_SCALE) / (double)M2);
            // reset for next graph replay
            g_acc   = 0;
            g_count = 0;
            __threadfence();
        }
    }
}

extern "C" void kernel_launch(void* const* d_in, const int* in_sizes, int n_in,
                              void* d_out, int out_size)
{
    const float4* src = (const float4*)d_in[0];
    const float4* tgt = (const float4*)d_in[1];
    float* out = (float*)d_out;

    mmd_fused_kernel<<<GRID, THREADS>>>(src, tgt, out);
}

// round 3
// speedup vs baseline: 1.3487x; 1.0495x over previous
#include <cuda_runtime.h>

// LinearTimeMMD fused single kernel: source/target [65536, 512] fp32 -> scalar.
// One warp per pair (32 threads x 4 float4/row = 512 floats/row).
// 8 pairs per 256-thread block; one fixed-point int64 atomic per block.

#define M2            32768
#define PAIRS_PER_BLK 8
#define THREADS       256
#define GRID          (M2 / PAIRS_PER_BLK)   // 4096
#define F4_PER_ROW    128                    // 512 floats / 4

// 2^40 fixed-point scale: |h| <= 10 -> |v| < 2^44; sum over 32768 < 2^59.
#define FP_SCALE      1099511627776.0

__device__ long long    g_acc   = 0;
__device__ unsigned int g_count = 0;

__global__ __launch_bounds__(THREADS)
void mmd_fused_kernel(const float4* __restrict__ src,
                      const float4* __restrict__ tgt,
                      float* __restrict__ out)
{
    const int t   = threadIdx.x;
    const int wid = t >> 5;                 // warp id in block = pair slot
    const int lid = t & 31;
    const int p   = blockIdx.x * PAIRS_PER_BLK + wid;

    const size_t ro = (size_t)(2 * p) * F4_PER_ROW;      // row 2p
    const size_t re = ro + F4_PER_ROW;                   // row 2p+1

    // Issue all 16 loads up front (max MLP), streaming hint (no reuse).
    float4 xo[4], xe[4], yo[4], ye[4];
    #pragma unroll
    for (int k = 0; k < 4; ++k) {
        const int c = lid + 32 * k;
        xo[k] = __ldcs(src + ro + c);
        xe[k] = __ldcs(src + re + c);
        yo[k] = __ldcs(tgt + ro + c);
        ye[k] = __ldcs(tgt + re + c);
    }

    float dxx = 0.f, dyy = 0.f, dxy = 0.f, dyx = 0.f;
    #pragma unroll
    for (int k = 0; k < 4; ++k) {
        float d;
        d = xo[k].x - xe[k].x; dxx = fmaf(d, d, dxx);
        d = xo[k].y - xe[k].y; dxx = fmaf(d, d, dxx);
        d = xo[k].z - xe[k].z; dxx = fmaf(d, d, dxx);
        d = xo[k].w - xe[k].w; dxx = fmaf(d, d, dxx);

        d = yo[k].x - ye[k].x; dyy = fmaf(d, d, dyy);
        d = yo[k].y - ye[k].y; dyy = fmaf(d, d, dyy);
        d = yo[k].z - ye[k].z; dyy = fmaf(d, d, dyy);
        d = yo[k].w - ye[k].w; dyy = fmaf(d, d, dyy);

        d = xo[k].x - ye[k].x; dxy = fmaf(d, d, dxy);
        d = xo[k].y - ye[k].y; dxy = fmaf(d, d, dxy);
        d = xo[k].z - ye[k].z; dxy = fmaf(d, d, dxy);
        d = xo[k].w - ye[k].w; dxy = fmaf(d, d, dxy);

        d = xe[k].x - yo[k].x; dyx = fmaf(d, d, dyx);
        d = xe[k].y - yo[k].y; dyx = fmaf(d, d, dyx);
        d = xe[k].z - yo[k].z; dyx = fmaf(d, d, dyx);
        d = xe[k].w - yo[k].w; dyx = fmaf(d, d, dyx);
    }

    // warp tree reduce (4 values) — warp == full reduction group
    #pragma unroll
    for (int off = 16; off > 0; off >>= 1) {
        dxx += __shfl_xor_sync(0xffffffffu, dxx, off);
        dyy += __shfl_xor_sync(0xffffffffu, dyy, off);
        dxy += __shfl_xor_sync(0xffffffffu, dxy, off);
        dyx += __shfl_xor_sync(0xffffffffu, dyx, off);
    }

    __shared__ long long h_fixed[PAIRS_PER_BLK];

    if (lid == 0) {
        // bw = sum/4 / KERNEL_MUL^(KERNEL_NUM/2) = sum/16
        float bw = (dxx + dyy + dxy + dyx) * (1.0f / 16.0f);
        float h = 0.f;
        float mult = 1.f;
        #pragma unroll
        for (int k = 0; k < 5; ++k) {
            float inv = 1.0f / (bw * mult + 1e-6f);
            h += expf(-dxx * inv) + expf(-dyy * inv)
               - expf(-dxy * inv) - expf(-dyx * inv);
            mult *= 2.f;
        }
        h_fixed[wid] = (long long)llrint((double)h * FP_SCALE);
    }
    __syncthreads();

    if (t == 0) {
        long long v = 0;
        #pragma unroll
        for (int w = 0; w < PAIRS_PER_BLK; ++w) v += h_fixed[w];
        atomicAdd((unsigned long long*)&g_acc, (unsigned long long)v);

        __threadfence();
        unsigned int done = atomicAdd(&g_count, 1u);
        if (done == GRID - 1) {
            long long acc = g_acc;
            out[0] = (float)(((double)acc / FP_SCALE) / (double)M2);
            // reset for next graph replay
            g_acc   = 0;
            g_count = 0;
            __threadfence();
        }
    }
}

extern "C" void kernel_launch(void* const* d_in, const int* in_sizes, int n_in,
                              void* d_out, int out_size)
{
    const float4* src = (const float4*)d_in[0];
    const float4* tgt = (const float4*)d_in[1];
    float* out = (float*)d_out;

    mmd_fused_kernel<<<GRID, THREADS>>>(src, tgt, out);
}

// round 4
// speedup vs baseline: 1.3951x; 1.0344x over previous
#include <cuda_runtime.h>

// LinearTimeMMD fused single kernel: source/target [65536, 512] fp32 -> scalar.
// One warp per pair; 4 chunks of 4 float4 loads, immediate accumulation
// (keeps regs <= 32 so __launch_bounds__(256,8) gives 64 warps/SM).
// 8 pairs per 256-thread block; one fixed-point int64 atomic per block.

#define M2            32768
#define PAIRS_PER_BLK 8
#define THREADS       256
#define GRID          (M2 / PAIRS_PER_BLK)   // 4096
#define F4_PER_ROW    128                    // 512 floats / 4

// 2^40 fixed-point scale: |h| <= 10 -> |v| < 2^44; sum over 32768 < 2^59.
#define FP_SCALE      1099511627776.0

__device__ long long    g_acc   = 0;
__device__ unsigned int g_count = 0;

__global__ __launch_bounds__(THREADS, 8)
void mmd_fused_kernel(const float4* __restrict__ src,
                      const float4* __restrict__ tgt,
                      float* __restrict__ out)
{
    const int t   = threadIdx.x;
    const int wid = t >> 5;                 // warp id in block = pair slot
    const int lid = t & 31;
    const int p   = blockIdx.x * PAIRS_PER_BLK + wid;

    const size_t ro = (size_t)(2 * p) * F4_PER_ROW;      // row 2p
    const size_t re = ro + F4_PER_ROW;                   // row 2p+1

    float dxx = 0.f, dyy = 0.f, dxy = 0.f, dyx = 0.f;

    #pragma unroll
    for (int k = 0; k < 4; ++k) {
        const int c = lid + 32 * k;
        const float4 xo = __ldcs(src + ro + c);
        const float4 xe = __ldcs(src + re + c);
        const float4 yo = __ldcs(tgt + ro + c);
        const float4 ye = __ldcs(tgt + re + c);

        float d;
        d = xo.x - xe.x; dxx = fmaf(d, d, dxx);
        d = xo.y - xe.y; dxx = fmaf(d, d, dxx);
        d = xo.z - xe.z; dxx = fmaf(d, d, dxx);
        d = xo.w - xe.w; dxx = fmaf(d, d, dxx);

        d = yo.x - ye.x; dyy = fmaf(d, d, dyy);
        d = yo.y - ye.y; dyy = fmaf(d, d, dyy);
        d = yo.z - ye.z; dyy = fmaf(d, d, dyy);
        d = yo.w - ye.w; dyy = fmaf(d, d, dyy);

        d = xo.x - ye.x; dxy = fmaf(d, d, dxy);
        d = xo.y - ye.y; dxy = fmaf(d, d, dxy);
        d = xo.z - ye.z; dxy = fmaf(d, d, dxy);
        d = xo.w - ye.w; dxy = fmaf(d, d, dxy);

        d = xe.x - yo.x; dyx = fmaf(d, d, dyx);
        d = xe.y - yo.y; dyx = fmaf(d, d, dyx);
        d = xe.z - yo.z; dyx = fmaf(d, d, dyx);
        d = xe.w - yo.w; dyx = fmaf(d, d, dyx);
    }

    // warp tree reduce (4 values) — warp == full reduction group
    #pragma unroll
    for (int off = 16; off > 0; off >>= 1) {
        dxx += __shfl_xor_sync(0xffffffffu, dxx, off);
        dyy += __shfl_xor_sync(0xffffffffu, dyy, off);
        dxy += __shfl_xor_sync(0xffffffffu, dxy, off);
        dyx += __shfl_xor_sync(0xffffffffu, dyx, off);
    }

    __shared__ long long h_fixed[PAIRS_PER_BLK];

    if (lid == 0) {
        // bw = sum/4 / KERNEL_MUL^(KERNEL_NUM/2) = sum/16
        float bw = (dxx + dyy + dxy + dyx) * (1.0f / 16.0f);
        float h = 0.f;
        float mult = 1.f;
        #pragma unroll
        for (int k = 0; k < 5; ++k) {
            float inv = 1.0f / (bw * mult + 1e-6f);
            h += expf(-dxx * inv) + expf(-dyy * inv)
               - expf(-dxy * inv) - expf(-dyx * inv);
            mult *= 2.f;
        }
        h_fixed[wid] = (long long)llrint((double)h * FP_SCALE);
    }
    __syncthreads();

    if (t == 0) {
        long long v = 0;
        #pragma unroll
        for (int w = 0; w < PAIRS_PER_BLK; ++w) v += h_fixed[w];
        atomicAdd((unsigned long long*)&g_acc, (unsigned long long)v);

        __threadfence();
        unsigned int done = atomicAdd(&g_count, 1u);
        if (done == GRID - 1) {
            long long acc = g_acc;
            out[0] = (float)(((double)acc / FP_SCALE) / (double)M2);
            // reset for next graph replay
            g_acc   = 0;
            g_count = 0;
            __threadfence();
        }
    }
}

extern "C" void kernel_launch(void* const* d_in, const int* in_sizes, int n_in,
                              void* d_out, int out_size)
{
    const float4* src = (const float4*)d_in[0];
    const float4* tgt = (const float4*)d_in[1];
    float* out = (float*)d_out;

    mmd_fused_kernel<<<GRID, THREADS>>>(src, tgt, out);
}